// round 1
// baseline (speedup 1.0000x reference)
#include <cuda_runtime.h>
#include <cuda_bf16.h>

// Problem constants (GLALayer: B=4, T=4096, D_MODEL=1024, H=16, S=64)
#define D_MODEL 1024
#define T_LEN   4096
#define BATCH   4
#define M_TOT   (BATCH * T_LEN)   // 16384 rows (b*T + t)
#define HS      1024              // N_HEADS * D_STATE
#define NGATES  2048              // 2 * HS

// Scratch (device globals; no allocation allowed in kernel_launch)
__device__ float g_gates[(size_t)M_TOT * NGATES]; // raw gate pre-activations [M, 2048]
__device__ float g_v[(size_t)M_TOT * HS];         // V [M, 1024]
__device__ float g_a[(size_t)M_TOT * HS];         // forget gate sigmoid
__device__ float g_bv[(size_t)M_TOT * HS];        // input gate sigmoid * V
__device__ float g_h[(size_t)M_TOT * HS];         // recurrent state sequence

// ---------------------------------------------------------------------------
// TN SGEMM: C[M,N] = A[M,K] * B[N,K]^T  (both operands row-major, K contiguous)
// 128x128 block tile, BK=8, 256 threads, 8x8 per-thread microtile.
// M, N, K all multiples of tile sizes here (16384, {1024,2048}, 1024).
// ---------------------------------------------------------------------------
#define BM 128
#define BN 128
#define BK 8
#define TM 8
#define TN 8

__global__ void __launch_bounds__(256, 2)
sgemm_tn(const float* __restrict__ A, const float* __restrict__ B,
         float* __restrict__ C, int N, int K) {
    __shared__ float As[BK][BM];
    __shared__ float Bs[BK][BN];

    const int bx = blockIdx.x;  // N tile
    const int by = blockIdx.y;  // M tile
    const int tid = threadIdx.x;
    const int tx = tid & 15;    // 0..15 -> N
    const int ty = tid >> 4;    // 0..15 -> M

    const float* Ab = A + (size_t)by * BM * K;
    const float* Bb = B + (size_t)bx * BN * K;

    // each thread loads one float4 of A and one of B per K-tile
    const int lr = tid >> 1;         // 0..127 row within tile
    const int lc = (tid & 1) * 4;    // 0 or 4 column within BK

    float acc[TM][TN];
#pragma unroll
    for (int i = 0; i < TM; i++)
#pragma unroll
        for (int j = 0; j < TN; j++) acc[i][j] = 0.0f;

    for (int k0 = 0; k0 < K; k0 += BK) {
        float4 av = *(const float4*)(Ab + (size_t)lr * K + k0 + lc);
        float4 bv = *(const float4*)(Bb + (size_t)lr * K + k0 + lc);
        As[lc + 0][lr] = av.x; As[lc + 1][lr] = av.y;
        As[lc + 2][lr] = av.z; As[lc + 3][lr] = av.w;
        Bs[lc + 0][lr] = bv.x; Bs[lc + 1][lr] = bv.y;
        Bs[lc + 2][lr] = bv.z; Bs[lc + 3][lr] = bv.w;
        __syncthreads();

#pragma unroll
        for (int k = 0; k < BK; k++) {
            float ar[TM], br[TN];
#pragma unroll
            for (int i = 0; i < TM; i++) ar[i] = As[k][ty * TM + i];
#pragma unroll
            for (int j = 0; j < TN; j++) br[j] = Bs[k][tx * TN + j];
#pragma unroll
            for (int i = 0; i < TM; i++)
#pragma unroll
                for (int j = 0; j < TN; j++)
                    acc[i][j] = fmaf(ar[i], br[j], acc[i][j]);
        }
        __syncthreads();
    }

    float* Cb = C + (size_t)(by * BM + ty * TM) * N + bx * BN + tx * TN;
#pragma unroll
    for (int i = 0; i < TM; i++) {
        float4 v0 = make_float4(acc[i][0], acc[i][1], acc[i][2], acc[i][3]);
        float4 v1 = make_float4(acc[i][4], acc[i][5], acc[i][6], acc[i][7]);
        *(float4*)(Cb + (size_t)i * N + 0) = v0;
        *(float4*)(Cb + (size_t)i * N + 4) = v1;
    }
}

// ---------------------------------------------------------------------------
// Elementwise: A = sigmoid(g[:, j] + b[j]); BV = sigmoid(g[:, 1024+j] + b[1024+j]) * V
// ---------------------------------------------------------------------------
__global__ void gate_elementwise(const float* __restrict__ gate_b) {
    size_t idx = (size_t)blockIdx.x * blockDim.x + threadIdx.x;
    if (idx >= (size_t)M_TOT * HS) return;
    size_t row = idx >> 10;      // / 1024
    int j = (int)(idx & 1023);
    float gf = g_gates[row * NGATES + j] + gate_b[j];
    float gi = g_gates[row * NGATES + HS + j] + gate_b[HS + j];
    float a = 1.0f / (1.0f + __expf(-gf));
    float bg = 1.0f / (1.0f + __expf(-gi));
    g_a[idx] = a;
    g_bv[idx] = bg * g_v[idx];
}

// ---------------------------------------------------------------------------
// Sequential scan over T: h_t = a_t * h_{t-1} + bv_t, per (b, j) chain.
// 4096 chains; loads are recurrence-independent -> unroll for MLP.
// ---------------------------------------------------------------------------
__global__ void scan_kernel(const float* __restrict__ h0,
                            float* __restrict__ hlast) {
    int idx = blockIdx.x * blockDim.x + threadIdx.x;  // 0..4095
    int b = idx >> 10;
    int j = idx & 1023;
    size_t base = ((size_t)b * T_LEN) << 10;  // * 1024
    const float* ap = g_a + base + j;
    const float* bp = g_bv + base + j;
    float* hp = g_h + base + j;
    float h = h0[idx];
#pragma unroll 8
    for (int t = 0; t < T_LEN; t++) {
        size_t off = (size_t)t << 10;
        h = fmaf(ap[off], h, bp[off]);
        hp[off] = h;
    }
    if (hlast) hlast[idx] = h;
}

// ---------------------------------------------------------------------------
extern "C" void kernel_launch(void* const* d_in, const int* in_sizes, int n_in,
                              void* d_out, int out_size) {
    const float* x       = (const float*)d_in[0];  // [B,T,D]
    const float* h_prev  = (const float*)d_in[1];  // [B,H,S]
    const float* gate_w  = (const float*)d_in[2];  // [2048, 1024]
    const float* gate_b  = (const float*)d_in[3];  // [2048]
    const float* value_w = (const float*)d_in[4];  // [1024, 1024]
    const float* out_w   = (const float*)d_in[5];  // [1024, 1024]
    float* out = (float*)d_out;

    float *p_gates, *p_v, *p_h;
    cudaGetSymbolAddress((void**)&p_gates, g_gates);
    cudaGetSymbolAddress((void**)&p_v, g_v);
    cudaGetSymbolAddress((void**)&p_h, g_h);

    // GEMM1a: gates = x @ gate_w^T   [16384 x 2048]
    {
        dim3 grid(NGATES / BN, M_TOT / BM);
        sgemm_tn<<<grid, 256>>>(x, gate_w, p_gates, NGATES, D_MODEL);
    }
    // GEMM1b: V = x @ value_w^T      [16384 x 1024]
    {
        dim3 grid(HS / BN, M_TOT / BM);
        sgemm_tn<<<grid, 256>>>(x, value_w, p_v, HS, D_MODEL);
    }
    // Elementwise gates
    {
        size_t n = (size_t)M_TOT * HS;
        gate_elementwise<<<(unsigned)((n + 255) / 256), 256>>>(gate_b);
    }
    // Scan (+ optional h_last tail in d_out if there is room for it)
    {
        float* hlast = nullptr;
        if ((size_t)out_size >= (size_t)M_TOT * D_MODEL + BATCH * HS)
            hlast = out + (size_t)M_TOT * D_MODEL;
        scan_kernel<<<BATCH * HS / 256, 256>>>(h_prev, hlast);
    }
    // GEMM2: y = h @ out_w^T         [16384 x 1024] written straight to d_out
    {
        dim3 grid(D_MODEL / BN, M_TOT / BM);
        sgemm_tn<<<grid, 256>>>(p_h, out_w, out, D_MODEL, D_MODEL);
    }
}

// round 3
// speedup vs baseline: 1.8167x; 1.8167x over previous
#include <cuda_runtime.h>
#include <cuda_bf16.h>
#include <cstdint>

// Problem constants (GLALayer: B=4, T=4096, D_MODEL=1024, H=16, S=64)
#define D_MODEL 1024
#define T_LEN   4096
#define BATCH   4
#define M_TOT   (BATCH * T_LEN)   // 16384
#define HS      1024
#define NGATES  2048

// Scratch (device globals)
__device__ float g_gates[(size_t)M_TOT * NGATES]; // gate pre-activations
__device__ float g_v[(size_t)M_TOT * HS];
__device__ float g_a[(size_t)M_TOT * HS];
__device__ float g_bv[(size_t)M_TOT * HS];
__device__ float g_h[(size_t)M_TOT * HS];         // tf32-rounded h sequence
__device__ float g_xc[(size_t)M_TOT * D_MODEL];   // tf32-rounded x
__device__ float g_gwc[(size_t)NGATES * D_MODEL]; // tf32-rounded gate_w
__device__ float g_vwc[(size_t)HS * D_MODEL];     // tf32-rounded value_w
__device__ float g_owc[(size_t)D_MODEL * HS];     // tf32-rounded out_w

// ---------------------------------------------------------------------------
__device__ __forceinline__ uint32_t smem_u32(const void* p) {
    uint32_t a;
    asm("{ .reg .u64 t; cvta.to.shared.u64 t, %1; cvt.u32.u64 %0, t; }"
        : "=r"(a) : "l"(p));
    return a;
}

__device__ __forceinline__ uint32_t f2tf32(float f) {
    uint32_t r;
    asm("cvt.rna.tf32.f32 %0, %1;" : "=r"(r) : "f"(f));
    return r;
}

__device__ __forceinline__ void cpasync16(uint32_t dst, const void* src) {
    asm volatile("cp.async.cg.shared.global [%0], [%1], 16;" :: "r"(dst), "l"(src));
}
#define CP_COMMIT()  asm volatile("cp.async.commit_group;" ::: "memory")
#define CP_WAIT(n)   asm volatile("cp.async.wait_group %0;" :: "n"(n) : "memory")

// m16n8k8 tf32 mma (inputs are pre-rounded tf32 bit patterns in f32 regs)
__device__ __forceinline__ void mma_tf32(float* c, const float* a, const float* b) {
    asm volatile(
        "mma.sync.aligned.m16n8k8.row.col.f32.tf32.tf32.f32 "
        "{%0,%1,%2,%3}, {%4,%5,%6,%7}, {%8,%9}, {%0,%1,%2,%3};"
        : "+f"(c[0]), "+f"(c[1]), "+f"(c[2]), "+f"(c[3])
        : "r"(__float_as_uint(a[0])), "r"(__float_as_uint(a[1])),
          "r"(__float_as_uint(a[2])), "r"(__float_as_uint(a[3])),
          "r"(__float_as_uint(b[0])), "r"(__float_as_uint(b[1])));
}

// ---------------------------------------------------------------------------
// TN GEMM via mma.sync tf32: C[M,N] = A[M,K] * B[N,K]^T
// 128x128x32 CTA tile, 256 thr, 8 warps (2x4), warp tile 64x32.
// A,B must be pre-rounded to tf32. M,N multiples of 128; K multiple of 32.
// Dynamic smem: 2 bufs * (128*36) floats per operand = 73728 B.
// ---------------------------------------------------------------------------
#define PADK 36
#define TILE_FLTS (128 * PADK)   // 4608

__global__ void __launch_bounds__(256, 2)
gemm_tf32_mma(const float* __restrict__ A, const float* __restrict__ B,
              float* __restrict__ C, int N, int K) {
    extern __shared__ float smem[];
    float* sA = smem;                 // + buf*TILE_FLTS
    float* sB = smem + 2 * TILE_FLTS;

    const int tid = threadIdx.x;
    const int lane = tid & 31;
    const int wid = tid >> 5;
    const int wm = (wid >> 2) * 64;   // warp M offset
    const int wn = (wid & 3) * 32;    // warp N offset
    const int g = lane >> 2;          // 0..7
    const int tg = lane & 3;          // 0..3

    const int bx = blockIdx.x, by = blockIdx.y;
    const float* Ab = A + (size_t)by * 128 * K;
    const float* Bb = B + (size_t)bx * 128 * K;

    const uint32_t sA_u = smem_u32(sA);
    const uint32_t sB_u = smem_u32(sB);

    float acc[4][4][4];
#pragma unroll
    for (int mi = 0; mi < 4; mi++)
#pragma unroll
        for (int ni = 0; ni < 4; ni++)
#pragma unroll
            for (int q = 0; q < 4; q++) acc[mi][ni][q] = 0.0f;

    const int NT = K / 32;

    // prefetch tile 0 into buf 0
    {
#pragma unroll
        for (int i = 0; i < 4; i++) {
            const int gid = tid + i * 256;          // 0..1023
            const int row = gid >> 3, kq = gid & 7; // row 0..127, 16B granule
            cpasync16(sA_u + (uint32_t)(row * PADK * 4 + kq * 16),
                      Ab + (size_t)row * K + kq * 4);
            cpasync16(sB_u + (uint32_t)(row * PADK * 4 + kq * 16),
                      Bb + (size_t)row * K + kq * 4);
        }
        CP_COMMIT();
    }

    int buf = 0;
    for (int kt = 0; kt < NT; kt++) {
        if (kt + 1 < NT) {
            const int kof = (kt + 1) * 32;
            const uint32_t boff = (uint32_t)((buf ^ 1) * TILE_FLTS * 4);
#pragma unroll
            for (int i = 0; i < 4; i++) {
                const int gid = tid + i * 256;
                const int row = gid >> 3, kq = gid & 7;
                cpasync16(sA_u + boff + (uint32_t)(row * PADK * 4 + kq * 16),
                          Ab + (size_t)row * K + kof + kq * 4);
                cpasync16(sB_u + boff + (uint32_t)(row * PADK * 4 + kq * 16),
                          Bb + (size_t)row * K + kof + kq * 4);
            }
            CP_COMMIT();
            CP_WAIT(1);
        } else {
            CP_WAIT(0);
        }
        __syncthreads();

        const float* sAb = sA + buf * TILE_FLTS;
        const float* sBb = sB + buf * TILE_FLTS;
#pragma unroll
        for (int ks = 0; ks < 4; ks++) {
            const int k0 = ks * 8;
            float af[4][4], bf[4][2];
#pragma unroll
            for (int mi = 0; mi < 4; mi++) {
                const int m = wm + mi * 16;
                af[mi][0] = sAb[(m + g) * PADK + k0 + tg];
                af[mi][1] = sAb[(m + g + 8) * PADK + k0 + tg];
                af[mi][2] = sAb[(m + g) * PADK + k0 + tg + 4];
                af[mi][3] = sAb[(m + g + 8) * PADK + k0 + tg + 4];
            }
#pragma unroll
            for (int ni = 0; ni < 4; ni++) {
                const int n = wn + ni * 8;
                bf[ni][0] = sBb[(n + g) * PADK + k0 + tg];
                bf[ni][1] = sBb[(n + g) * PADK + k0 + tg + 4];
            }
#pragma unroll
            for (int mi = 0; mi < 4; mi++)
#pragma unroll
                for (int ni = 0; ni < 4; ni++)
                    mma_tf32(acc[mi][ni], af[mi], bf[ni]);
        }
        __syncthreads();
        buf ^= 1;
    }

    // Epilogue
#pragma unroll
    for (int mi = 0; mi < 4; mi++) {
        const int row0 = by * 128 + wm + mi * 16 + g;
#pragma unroll
        for (int ni = 0; ni < 4; ni++) {
            const int col = bx * 128 + wn + ni * 8 + 2 * tg;
            *(float2*)(C + (size_t)row0 * N + col) =
                make_float2(acc[mi][ni][0], acc[mi][ni][1]);
            *(float2*)(C + (size_t)(row0 + 8) * N + col) =
                make_float2(acc[mi][ni][2], acc[mi][ni][3]);
        }
    }
}

// ---------------------------------------------------------------------------
// Elementwise convert to tf32-rounded f32 (rna, unbiased)
// ---------------------------------------------------------------------------
__global__ void convert_tf32(const float* __restrict__ src,
                             float* __restrict__ dst, int n4) {
    int i = blockIdx.x * blockDim.x + threadIdx.x;
    if (i >= n4) return;
    float4 v = ((const float4*)src)[i];
    uint4 o = make_uint4(f2tf32(v.x), f2tf32(v.y), f2tf32(v.z), f2tf32(v.w));
    ((uint4*)dst)[i] = o;
}

// ---------------------------------------------------------------------------
// Elementwise gates
// ---------------------------------------------------------------------------
__global__ void gate_elementwise(const float* __restrict__ gate_b) {
    size_t idx = (size_t)blockIdx.x * blockDim.x + threadIdx.x;
    if (idx >= (size_t)M_TOT * HS) return;
    size_t row = idx >> 10;
    int j = (int)(idx & 1023);
    float gf = g_gates[row * NGATES + j] + gate_b[j];
    float gi = g_gates[row * NGATES + HS + j] + gate_b[HS + j];
    float a = 1.0f / (1.0f + __expf(-gf));
    float bg = 1.0f / (1.0f + __expf(-gi));
    g_a[idx] = a;
    g_bv[idx] = bg * g_v[idx];
}

// ---------------------------------------------------------------------------
// Sequential scan; h kept fp32, stored tf32-rounded (GEMM2 input)
// ---------------------------------------------------------------------------
__global__ void scan_kernel(const float* __restrict__ h0,
                            float* __restrict__ hlast) {
    int idx = blockIdx.x * blockDim.x + threadIdx.x;  // 0..4095
    int b = idx >> 10;
    int j = idx & 1023;
    size_t base = ((size_t)b * T_LEN) << 10;
    const float* ap = g_a + base + j;
    const float* bp = g_bv + base + j;
    float* hp = g_h + base + j;
    float h = h0[idx];
#pragma unroll 8
    for (int t = 0; t < T_LEN; t++) {
        size_t off = (size_t)t << 10;
        h = fmaf(ap[off], h, bp[off]);
        hp[off] = __uint_as_float(f2tf32(h));
    }
    if (hlast) hlast[idx] = h;
}

// ---------------------------------------------------------------------------
extern "C" void kernel_launch(void* const* d_in, const int* in_sizes, int n_in,
                              void* d_out, int out_size) {
    const float* x       = (const float*)d_in[0];
    const float* h_prev  = (const float*)d_in[1];
    const float* gate_w  = (const float*)d_in[2];
    const float* gate_b  = (const float*)d_in[3];
    const float* value_w = (const float*)d_in[4];
    const float* out_w   = (const float*)d_in[5];
    float* out = (float*)d_out;

    float *p_gates, *p_v, *p_h, *p_xc, *p_gwc, *p_vwc, *p_owc;
    cudaGetSymbolAddress((void**)&p_gates, g_gates);
    cudaGetSymbolAddress((void**)&p_v, g_v);
    cudaGetSymbolAddress((void**)&p_h, g_h);
    cudaGetSymbolAddress((void**)&p_xc, g_xc);
    cudaGetSymbolAddress((void**)&p_gwc, g_gwc);
    cudaGetSymbolAddress((void**)&p_vwc, g_vwc);
    cudaGetSymbolAddress((void**)&p_owc, g_owc);

    static bool attr_done = false;
    if (!attr_done) {
        cudaFuncSetAttribute(gemm_tf32_mma,
                             cudaFuncAttributeMaxDynamicSharedMemorySize, 73728);
        attr_done = true;
    }
    const size_t SMEM = 73728;

    // tf32 pre-rounding passes
    {
        int n4;
        n4 = (M_TOT * D_MODEL) / 4;
        convert_tf32<<<(n4 + 255) / 256, 256>>>(x, p_xc, n4);
        n4 = (NGATES * D_MODEL) / 4;
        convert_tf32<<<(n4 + 255) / 256, 256>>>(gate_w, p_gwc, n4);
        n4 = (HS * D_MODEL) / 4;
        convert_tf32<<<(n4 + 255) / 256, 256>>>(value_w, p_vwc, n4);
        n4 = (D_MODEL * HS) / 4;
        convert_tf32<<<(n4 + 255) / 256, 256>>>(out_w, p_owc, n4);
    }
    // GEMM1a: gates = x @ gate_w^T   [16384 x 2048]
    {
        dim3 grid(NGATES / 128, M_TOT / 128);
        gemm_tf32_mma<<<grid, 256, SMEM>>>(p_xc, p_gwc, p_gates, NGATES, D_MODEL);
    }
    // GEMM1b: V = x @ value_w^T      [16384 x 1024]
    {
        dim3 grid(HS / 128, M_TOT / 128);
        gemm_tf32_mma<<<grid, 256, SMEM>>>(p_xc, p_vwc, p_v, HS, D_MODEL);
    }
    // Elementwise gates
    {
        size_t n = (size_t)M_TOT * HS;
        gate_elementwise<<<(unsigned)((n + 255) / 256), 256>>>(gate_b);
    }
    // Scan (+ h_last tail in d_out if room)
    {
        float* hlast = nullptr;
        if ((size_t)out_size >= (size_t)M_TOT * D_MODEL + BATCH * HS)
            hlast = out + (size_t)M_TOT * D_MODEL;
        scan_kernel<<<BATCH * HS / 256, 256>>>(h_prev, hlast);
    }
    // GEMM2: y = h @ out_w^T         [16384 x 1024]
    {
        dim3 grid(D_MODEL / 128, M_TOT / 128);
        gemm_tf32_mma<<<grid, 256, SMEM>>>(p_h, p_owc, out, D_MODEL, D_MODEL);
    }
}

// round 4
// speedup vs baseline: 4.1839x; 2.3030x over previous
#include <cuda_runtime.h>
#include <cuda_bf16.h>
#include <cstdint>

// Problem constants (GLALayer: B=4, T=4096, D_MODEL=1024, H=16, S=64)
#define D_MODEL 1024
#define T_LEN   4096
#define BATCH   4
#define M_TOT   (BATCH * T_LEN)   // 16384
#define HS      1024
#define NGATES  2048

#define NSEG    16
#define SEGLEN  (T_LEN / NSEG)    // 256

// Scratch (device globals)
__device__ float g_gates[(size_t)M_TOT * NGATES];
__device__ float g_v[(size_t)M_TOT * HS];
__device__ float g_a[(size_t)M_TOT * HS];
__device__ float g_bv[(size_t)M_TOT * HS];
__device__ float g_h[(size_t)M_TOT * HS];
__device__ float g_xc[(size_t)M_TOT * D_MODEL];
__device__ float g_gwc[(size_t)NGATES * D_MODEL];
__device__ float g_vwc[(size_t)HS * D_MODEL];
__device__ float g_owc[(size_t)D_MODEL * HS];
__device__ float g_segP[BATCH * NSEG * HS];  // per-segment product of a
__device__ float g_segH[BATCH * NSEG * HS];  // per-segment local end h
__device__ float g_segS[BATCH * NSEG * HS];  // resolved segment start state

// ---------------------------------------------------------------------------
__device__ __forceinline__ uint32_t smem_u32(const void* p) {
    uint32_t a;
    asm("{ .reg .u64 t; cvta.to.shared.u64 t, %1; cvt.u32.u64 %0, t; }"
        : "=r"(a) : "l"(p));
    return a;
}

__device__ __forceinline__ uint32_t f2tf32(float f) {
    uint32_t r;
    asm("cvt.rna.tf32.f32 %0, %1;" : "=r"(r) : "f"(f));
    return r;
}

__device__ __forceinline__ void cpasync16(uint32_t dst, const void* src) {
    asm volatile("cp.async.cg.shared.global [%0], [%1], 16;" :: "r"(dst), "l"(src));
}
#define CP_COMMIT()  asm volatile("cp.async.commit_group;" ::: "memory")
#define CP_WAIT(n)   asm volatile("cp.async.wait_group %0;" :: "n"(n) : "memory")

// m16n8k8 tf32 mma (inputs are pre-rounded tf32 bit patterns in f32 regs)
__device__ __forceinline__ void mma_tf32(float* c, const float* a, const float* b) {
    asm volatile(
        "mma.sync.aligned.m16n8k8.row.col.f32.tf32.tf32.f32 "
        "{%0,%1,%2,%3}, {%4,%5,%6,%7}, {%8,%9}, {%0,%1,%2,%3};"
        : "+f"(c[0]), "+f"(c[1]), "+f"(c[2]), "+f"(c[3])
        : "r"(__float_as_uint(a[0])), "r"(__float_as_uint(a[1])),
          "r"(__float_as_uint(a[2])), "r"(__float_as_uint(a[3])),
          "r"(__float_as_uint(b[0])), "r"(__float_as_uint(b[1])));
}

// ---------------------------------------------------------------------------
// TN GEMM via mma.sync tf32: C[M,N] = A[M,K] * B[N,K]^T
// 128x128 CTA tile, 256 thr, warp tile 64x32 (2x4 warps).
// 4-stage cp.async pipeline, 16-K stage granularity.
// A,B must be pre-rounded to tf32. M,N mult of 128; K mult of 64.
// ---------------------------------------------------------------------------
#define KT     16
#define PADK2  20
#define STG_FLTS (128 * PADK2)   // 2560 floats per operand stage
#define NSTAGE 4
// dyn smem: NSTAGE * STG_FLTS * 2 operands * 4B = 81920 B

__global__ void __launch_bounds__(256, 2)
gemm_tf32_mma(const float* __restrict__ A, const float* __restrict__ B,
              float* __restrict__ C, int N, int K) {
    extern __shared__ float smem[];
    float* sA = smem;                        // [NSTAGE][STG_FLTS]
    float* sB = smem + NSTAGE * STG_FLTS;

    const int tid = threadIdx.x;
    const int lane = tid & 31;
    const int wid = tid >> 5;
    const int wm = (wid >> 2) * 64;
    const int wn = (wid & 3) * 32;
    const int g = lane >> 2;
    const int tg = lane & 3;

    const int bx = blockIdx.x, by = blockIdx.y;
    const float* Ab = A + (size_t)by * 128 * K;
    const float* Bb = B + (size_t)bx * 128 * K;

    const uint32_t sA_u = smem_u32(sA);
    const uint32_t sB_u = smem_u32(sB);

    // per-thread load coords: 2 granules per operand per stage
    const int row_l0 = tid >> 2;             // gid = tid      -> rows 0..63
    const int row_l1 = (tid + 256) >> 2;     // gid = tid+256  -> rows 64..127
    const int kq = (tid & 3) * 4;            // float offset within 16-float stage

    float acc[4][4][4];
#pragma unroll
    for (int mi = 0; mi < 4; mi++)
#pragma unroll
        for (int ni = 0; ni < 4; ni++)
#pragma unroll
            for (int q = 0; q < 4; q++) acc[mi][ni][q] = 0.0f;

    const int NT = K / KT;   // 64 for K=1024

    // issue a stage load (tile index kt -> stage kt % NSTAGE)
    auto issue_stage = [&](int kt) {
        const int kof = kt * KT;
        const uint32_t soff = (uint32_t)((kt & (NSTAGE - 1)) * STG_FLTS * 4);
        cpasync16(sA_u + soff + (uint32_t)((row_l0 * PADK2 + kq) * 4),
                  Ab + (size_t)row_l0 * K + kof + kq);
        cpasync16(sA_u + soff + (uint32_t)((row_l1 * PADK2 + kq) * 4),
                  Ab + (size_t)row_l1 * K + kof + kq);
        cpasync16(sB_u + soff + (uint32_t)((row_l0 * PADK2 + kq) * 4),
                  Bb + (size_t)row_l0 * K + kof + kq);
        cpasync16(sB_u + soff + (uint32_t)((row_l1 * PADK2 + kq) * 4),
                  Bb + (size_t)row_l1 * K + kof + kq);
        CP_COMMIT();
    };

    // prologue: fill 3 stages
    issue_stage(0);
    issue_stage(1);
    issue_stage(2);

    for (int kt = 0; kt < NT; kt++) {
        CP_WAIT(2);          // oldest (kt) complete
        __syncthreads();

        const float* sAb = sA + (kt & (NSTAGE - 1)) * STG_FLTS;
        const float* sBb = sB + (kt & (NSTAGE - 1)) * STG_FLTS;
#pragma unroll
        for (int ks = 0; ks < 2; ks++) {
            const int k0 = ks * 8;
            float af[4][4], bf[4][2];
#pragma unroll
            for (int mi = 0; mi < 4; mi++) {
                const int m = wm + mi * 16;
                af[mi][0] = sAb[(m + g) * PADK2 + k0 + tg];
                af[mi][1] = sAb[(m + g + 8) * PADK2 + k0 + tg];
                af[mi][2] = sAb[(m + g) * PADK2 + k0 + tg + 4];
                af[mi][3] = sAb[(m + g + 8) * PADK2 + k0 + tg + 4];
            }
#pragma unroll
            for (int ni = 0; ni < 4; ni++) {
                const int n = wn + ni * 8;
                bf[ni][0] = sBb[(n + g) * PADK2 + k0 + tg];
                bf[ni][1] = sBb[(n + g) * PADK2 + k0 + tg + 4];
            }
#pragma unroll
            for (int mi = 0; mi < 4; mi++)
#pragma unroll
                for (int ni = 0; ni < 4; ni++)
                    mma_tf32(acc[mi][ni], af[mi], bf[ni]);
        }
        __syncthreads();     // all reads of stage (kt+3)%4's previous use done
        if (kt + 3 < NT) issue_stage(kt + 3);
    }

    // Epilogue
#pragma unroll
    for (int mi = 0; mi < 4; mi++) {
        const int row0 = by * 128 + wm + mi * 16 + g;
#pragma unroll
        for (int ni = 0; ni < 4; ni++) {
            const int col = bx * 128 + wn + ni * 8 + 2 * tg;
            *(float2*)(C + (size_t)row0 * N + col) =
                make_float2(acc[mi][ni][0], acc[mi][ni][1]);
            *(float2*)(C + (size_t)(row0 + 8) * N + col) =
                make_float2(acc[mi][ni][2], acc[mi][ni][3]);
        }
    }
}

// ---------------------------------------------------------------------------
// Elementwise convert to tf32-rounded f32 (rna, unbiased)
// ---------------------------------------------------------------------------
__global__ void convert_tf32(const float* __restrict__ src,
                             float* __restrict__ dst, int n4) {
    int i = blockIdx.x * blockDim.x + threadIdx.x;
    if (i >= n4) return;
    float4 v = ((const float4*)src)[i];
    uint4 o = make_uint4(f2tf32(v.x), f2tf32(v.y), f2tf32(v.z), f2tf32(v.w));
    ((uint4*)dst)[i] = o;
}

// ---------------------------------------------------------------------------
// Elementwise gates
// ---------------------------------------------------------------------------
__global__ void gate_elementwise(const float* __restrict__ gate_b) {
    size_t idx = (size_t)blockIdx.x * blockDim.x + threadIdx.x;
    if (idx >= (size_t)M_TOT * HS) return;
    size_t row = idx >> 10;
    int j = (int)(idx & 1023);
    float gf = g_gates[row * NGATES + j] + gate_b[j];
    float gi = g_gates[row * NGATES + HS + j] + gate_b[HS + j];
    float a = 1.0f / (1.0f + __expf(-gf));
    float bg = 1.0f / (1.0f + __expf(-gi));
    g_a[idx] = a;
    g_bv[idx] = bg * g_v[idx];
}

// ---------------------------------------------------------------------------
// Segmented scan, pass 1: local scan per (b, seg, j) with h_start = 0.
// Stores local h (unrounded), per-segment a-product and local end state.
// ---------------------------------------------------------------------------
__global__ void scan_pass1() {
    int idx = blockIdx.x * blockDim.x + threadIdx.x;   // 0..65535
    int j = idx & 1023;
    int s = (idx >> 10) & (NSEG - 1);
    int b = idx >> (10 + 4);
    size_t base = (((size_t)b * T_LEN + (size_t)s * SEGLEN) << 10) + j;
    const float* ap = g_a + base;
    const float* bp = g_bv + base;
    float* hp = g_h + base;
    float h = 0.0f, P = 1.0f;
#pragma unroll 4
    for (int t = 0; t < SEGLEN; t++) {
        size_t off = (size_t)t << 10;
        float a = ap[off];
        h = fmaf(a, h, bp[off]);
        P *= a;
        hp[off] = h;
    }
    g_segP[idx] = P;
    g_segH[idx] = h;
}

// ---------------------------------------------------------------------------
// Pass 2: resolve segment start states sequentially (tiny).
// ---------------------------------------------------------------------------
__global__ void scan_pass2(const float* __restrict__ h0,
                           float* __restrict__ hlast) {
    int idx = blockIdx.x * blockDim.x + threadIdx.x;   // 0..4095
    int b = idx >> 10;
    int j = idx & 1023;
    float hs = h0[idx];
#pragma unroll
    for (int s = 0; s < NSEG; s++) {
        int k = ((b * NSEG + s) << 10) + j;
        g_segS[k] = hs;
        hs = fmaf(g_segP[k], hs, g_segH[k]);
    }
    if (hlast) hlast[idx] = hs;
}

// ---------------------------------------------------------------------------
// Pass 3: fixup h_t = local_t + (prod a[0..t]) * h_segstart; store tf32-rounded.
// ---------------------------------------------------------------------------
__global__ void scan_pass3() {
    int idx = blockIdx.x * blockDim.x + threadIdx.x;   // 0..65535
    int j = idx & 1023;
    int s = (idx >> 10) & (NSEG - 1);
    int b = idx >> (10 + 4);
    float hs = g_segS[idx];
    size_t base = (((size_t)b * T_LEN + (size_t)s * SEGLEN) << 10) + j;
    const float* ap = g_a + base;
    float* hp = g_h + base;
    float P = 1.0f;
#pragma unroll 4
    for (int t = 0; t < SEGLEN; t++) {
        size_t off = (size_t)t << 10;
        P *= ap[off];
        float h = fmaf(P, hs, hp[off]);
        hp[off] = __uint_as_float(f2tf32(h));
    }
}

// ---------------------------------------------------------------------------
extern "C" void kernel_launch(void* const* d_in, const int* in_sizes, int n_in,
                              void* d_out, int out_size) {
    const float* x       = (const float*)d_in[0];
    const float* h_prev  = (const float*)d_in[1];
    const float* gate_w  = (const float*)d_in[2];
    const float* gate_b  = (const float*)d_in[3];
    const float* value_w = (const float*)d_in[4];
    const float* out_w   = (const float*)d_in[5];
    float* out = (float*)d_out;

    float *p_gates, *p_v, *p_h, *p_xc, *p_gwc, *p_vwc, *p_owc;
    cudaGetSymbolAddress((void**)&p_gates, g_gates);
    cudaGetSymbolAddress((void**)&p_v, g_v);
    cudaGetSymbolAddress((void**)&p_h, g_h);
    cudaGetSymbolAddress((void**)&p_xc, g_xc);
    cudaGetSymbolAddress((void**)&p_gwc, g_gwc);
    cudaGetSymbolAddress((void**)&p_vwc, g_vwc);
    cudaGetSymbolAddress((void**)&p_owc, g_owc);

    static bool attr_done = false;
    if (!attr_done) {
        cudaFuncSetAttribute(gemm_tf32_mma,
                             cudaFuncAttributeMaxDynamicSharedMemorySize,
                             NSTAGE * STG_FLTS * 2 * 4);
        attr_done = true;
    }
    const size_t SMEM = NSTAGE * STG_FLTS * 2 * 4;   // 81920

    // tf32 pre-rounding passes
    {
        int n4;
        n4 = (M_TOT * D_MODEL) / 4;
        convert_tf32<<<(n4 + 255) / 256, 256>>>(x, p_xc, n4);
        n4 = (NGATES * D_MODEL) / 4;
        convert_tf32<<<(n4 + 255) / 256, 256>>>(gate_w, p_gwc, n4);
        n4 = (HS * D_MODEL) / 4;
        convert_tf32<<<(n4 + 255) / 256, 256>>>(value_w, p_vwc, n4);
        n4 = (D_MODEL * HS) / 4;
        convert_tf32<<<(n4 + 255) / 256, 256>>>(out_w, p_owc, n4);
    }
    // GEMM1a: gates = x @ gate_w^T   [16384 x 2048]
    {
        dim3 grid(NGATES / 128, M_TOT / 128);
        gemm_tf32_mma<<<grid, 256, SMEM>>>(p_xc, p_gwc, p_gates, NGATES, D_MODEL);
    }
    // GEMM1b: V = x @ value_w^T      [16384 x 1024]
    {
        dim3 grid(HS / 128, M_TOT / 128);
        gemm_tf32_mma<<<grid, 256, SMEM>>>(p_xc, p_vwc, p_v, HS, D_MODEL);
    }
    // Elementwise gates
    {
        size_t n = (size_t)M_TOT * HS;
        gate_elementwise<<<(unsigned)((n + 255) / 256), 256>>>(gate_b);
    }
    // Segmented scan
    {
        float* hlast = nullptr;
        if ((size_t)out_size >= (size_t)M_TOT * D_MODEL + BATCH * HS)
            hlast = out + (size_t)M_TOT * D_MODEL;
        scan_pass1<<<(BATCH * NSEG * HS) / 256, 256>>>();
        scan_pass2<<<(BATCH * HS) / 256, 256>>>(h_prev, hlast);
        scan_pass3<<<(BATCH * NSEG * HS) / 256, 256>>>();
    }
    // GEMM2: y = h @ out_w^T         [16384 x 1024]
    {
        dim3 grid(D_MODEL / 128, M_TOT / 128);
        gemm_tf32_mma<<<grid, 256, SMEM>>>(p_h, p_owc, out, D_MODEL, D_MODEL);
    }
}

// round 5
// speedup vs baseline: 4.2753x; 1.0218x over previous
#include <cuda_runtime.h>
#include <cuda_bf16.h>
#include <cstdint>

// Problem constants (GLALayer: B=4, T=4096, D_MODEL=1024, H=16, S=64)
#define D_MODEL 1024
#define T_LEN   4096
#define BATCH   4
#define M_TOT   (BATCH * T_LEN)   // 16384
#define HS      1024
#define NGATES  2048

#define NSEG    16
#define SEGLEN  (T_LEN / NSEG)    // 256

// Scratch (device globals)
__device__ float g_gates[(size_t)M_TOT * NGATES];
__device__ float g_v[(size_t)M_TOT * HS];
__device__ float g_a[(size_t)M_TOT * HS];
__device__ float g_h[(size_t)M_TOT * HS];
__device__ float g_xc[(size_t)M_TOT * D_MODEL];
__device__ float g_gwc[(size_t)NGATES * D_MODEL];
__device__ float g_vwc[(size_t)HS * D_MODEL];
__device__ float g_owc[(size_t)D_MODEL * HS];
__device__ float g_segP[BATCH * NSEG * HS];
__device__ float g_segH[BATCH * NSEG * HS];
__device__ float g_segS[BATCH * NSEG * HS];

// ---------------------------------------------------------------------------
__device__ __forceinline__ uint32_t smem_u32(const void* p) {
    uint32_t a;
    asm("{ .reg .u64 t; cvta.to.shared.u64 t, %1; cvt.u32.u64 %0, t; }"
        : "=r"(a) : "l"(p));
    return a;
}

__device__ __forceinline__ uint32_t f2tf32(float f) {
    uint32_t r;
    asm("cvt.rna.tf32.f32 %0, %1;" : "=r"(r) : "f"(f));
    return r;
}

__device__ __forceinline__ void cpasync16(uint32_t dst, const void* src) {
    asm volatile("cp.async.cg.shared.global [%0], [%1], 16;" :: "r"(dst), "l"(src));
}
#define CP_COMMIT()  asm volatile("cp.async.commit_group;" ::: "memory")
#define CP_WAIT(n)   asm volatile("cp.async.wait_group %0;" :: "n"(n) : "memory")

__device__ __forceinline__ void mma_tf32(float* c, const float* a, const float* b) {
    asm volatile(
        "mma.sync.aligned.m16n8k8.row.col.f32.tf32.tf32.f32 "
        "{%0,%1,%2,%3}, {%4,%5,%6,%7}, {%8,%9}, {%0,%1,%2,%3};"
        : "+f"(c[0]), "+f"(c[1]), "+f"(c[2]), "+f"(c[3])
        : "r"(__float_as_uint(a[0])), "r"(__float_as_uint(a[1])),
          "r"(__float_as_uint(a[2])), "r"(__float_as_uint(a[3])),
          "r"(__float_as_uint(b[0])), "r"(__float_as_uint(b[1])));
}

// ---------------------------------------------------------------------------
// TN GEMM via mma.sync tf32, fused dual-output variant:
// N-tiles [0, nsplit) come from B1 -> C1 (width N1); rest from B2 -> C2 (N2).
// CTA tile 128x128, 128 threads, 4 warps (2x2), warp tile 64x64.
// 4-stage cp.async pipeline at 16-K granularity. K mult of 64.
// ---------------------------------------------------------------------------
#define KT     16
#define PADK2  20
#define STG_FLTS (128 * PADK2)   // 2560
#define NSTAGE 4
// dyn smem: NSTAGE * STG_FLTS * 2 * 4B = 81920

__global__ void __launch_bounds__(128, 2)
gemm_tf32_mma(const float* __restrict__ A,
              const float* __restrict__ B1, const float* __restrict__ B2,
              float* __restrict__ C1, float* __restrict__ C2,
              int nsplit, int N1, int N2, int K) {
    extern __shared__ float smem[];
    float* sA = smem;
    float* sB = smem + NSTAGE * STG_FLTS;

    const int tid = threadIdx.x;
    const int lane = tid & 31;
    const int wid = tid >> 5;
    const int wm = (wid >> 1) * 64;
    const int wn = (wid & 1) * 64;
    const int g = lane >> 2;
    const int tg = lane & 3;

    const int bx = blockIdx.x, by = blockIdx.y;

    const float* Bb;
    float* Cout;
    int Nout, colbase;
    if (bx < nsplit) {
        Bb = B1 + (size_t)bx * 128 * K;
        Cout = C1; Nout = N1; colbase = bx * 128;
    } else {
        Bb = B2 + (size_t)(bx - nsplit) * 128 * K;
        Cout = C2; Nout = N2; colbase = (bx - nsplit) * 128;
    }
    const float* Ab = A + (size_t)by * 128 * K;

    const uint32_t sA_u = smem_u32(sA);
    const uint32_t sB_u = smem_u32(sB);

    float acc[4][8][4];
#pragma unroll
    for (int mi = 0; mi < 4; mi++)
#pragma unroll
        for (int ni = 0; ni < 8; ni++)
#pragma unroll
            for (int q = 0; q < 4; q++) acc[mi][ni][q] = 0.0f;

    const int NT = K / KT;

    // stage load: 512 granules (16B) per operand over 128 threads = 4 each
    auto issue_stage = [&](int kt) {
        const int kof = kt * KT;
        const uint32_t soff = (uint32_t)((kt & (NSTAGE - 1)) * STG_FLTS * 4);
#pragma unroll
        for (int i = 0; i < 4; i++) {
            const int gid = tid + i * 128;      // 0..511
            const int row = gid >> 2;
            const int kq = (gid & 3) * 4;
            cpasync16(sA_u + soff + (uint32_t)((row * PADK2 + kq) * 4),
                      Ab + (size_t)row * K + kof + kq);
            cpasync16(sB_u + soff + (uint32_t)((row * PADK2 + kq) * 4),
                      Bb + (size_t)row * K + kof + kq);
        }
        CP_COMMIT();
    };

    issue_stage(0);
    issue_stage(1);
    issue_stage(2);

    for (int kt = 0; kt < NT; kt++) {
        CP_WAIT(2);
        __syncthreads();

        const float* sAb = sA + (kt & (NSTAGE - 1)) * STG_FLTS;
        const float* sBb = sB + (kt & (NSTAGE - 1)) * STG_FLTS;
#pragma unroll
        for (int ks = 0; ks < 2; ks++) {
            const int k0 = ks * 8;
            float af[4][4], bf[8][2];
#pragma unroll
            for (int mi = 0; mi < 4; mi++) {
                const int m = wm + mi * 16;
                af[mi][0] = sAb[(m + g) * PADK2 + k0 + tg];
                af[mi][1] = sAb[(m + g + 8) * PADK2 + k0 + tg];
                af[mi][2] = sAb[(m + g) * PADK2 + k0 + tg + 4];
                af[mi][3] = sAb[(m + g + 8) * PADK2 + k0 + tg + 4];
            }
#pragma unroll
            for (int ni = 0; ni < 8; ni++) {
                const int n = wn + ni * 8;
                bf[ni][0] = sBb[(n + g) * PADK2 + k0 + tg];
                bf[ni][1] = sBb[(n + g) * PADK2 + k0 + tg + 4];
            }
#pragma unroll
            for (int mi = 0; mi < 4; mi++)
#pragma unroll
                for (int ni = 0; ni < 8; ni++)
                    mma_tf32(acc[mi][ni], af[mi], bf[ni]);
        }
        __syncthreads();
        if (kt + 3 < NT) issue_stage(kt + 3);
    }

    // Epilogue
#pragma unroll
    for (int mi = 0; mi < 4; mi++) {
        const int row0 = by * 128 + wm + mi * 16 + g;
#pragma unroll
        for (int ni = 0; ni < 8; ni++) {
            const int col = colbase + wn + ni * 8 + 2 * tg;
            *(float2*)(Cout + (size_t)row0 * Nout + col) =
                make_float2(acc[mi][ni][0], acc[mi][ni][1]);
            *(float2*)(Cout + (size_t)(row0 + 8) * Nout + col) =
                make_float2(acc[mi][ni][2], acc[mi][ni][3]);
        }
    }
}

// ---------------------------------------------------------------------------
__global__ void convert_tf32(const float* __restrict__ src,
                             float* __restrict__ dst, int n4) {
    int i = blockIdx.x * blockDim.x + threadIdx.x;
    if (i >= n4) return;
    float4 v = ((const float4*)src)[i];
    uint4 o = make_uint4(f2tf32(v.x), f2tf32(v.y), f2tf32(v.z), f2tf32(v.w));
    ((uint4*)dst)[i] = o;
}

// ---------------------------------------------------------------------------
// Segmented scan, pass 1 (fused sigmoid): reads raw gates + V, computes
// a = sigm(gf), bv = sigm(gi)*v in-register; local scan with h_start = 0.
// Writes a (for pass 3), local h, per-segment (P, Hend).
// ---------------------------------------------------------------------------
__global__ void scan_pass1(const float* __restrict__ gate_b) {
    int idx = blockIdx.x * blockDim.x + threadIdx.x;   // 0..65535
    int j = idx & 1023;
    int s = (idx >> 10) & (NSEG - 1);
    int b = idx >> (10 + 4);
    size_t row0 = (size_t)b * T_LEN + (size_t)s * SEGLEN;
    const float* gp = g_gates + row0 * NGATES + j;
    const float* vp = g_v + (row0 << 10) + j;
    float* ap_o = g_a + (row0 << 10) + j;
    float* hp = g_h + (row0 << 10) + j;
    const float bfg = gate_b[j];
    const float big = gate_b[HS + j];
    float h = 0.0f, P = 1.0f;
#pragma unroll 4
    for (int t = 0; t < SEGLEN; t++) {
        float gf = gp[(size_t)t * NGATES] + bfg;
        float gi = gp[(size_t)t * NGATES + HS] + big;
        float a = 1.0f / (1.0f + __expf(-gf));
        float bg = 1.0f / (1.0f + __expf(-gi));
        float bv = bg * vp[(size_t)t << 10];
        h = fmaf(a, h, bv);
        P *= a;
        ap_o[(size_t)t << 10] = a;
        hp[(size_t)t << 10] = h;
    }
    g_segP[idx] = P;
    g_segH[idx] = h;
}

// ---------------------------------------------------------------------------
__global__ void scan_pass2(const float* __restrict__ h0,
                           float* __restrict__ hlast) {
    int idx = blockIdx.x * blockDim.x + threadIdx.x;   // 0..4095
    int b = idx >> 10;
    int j = idx & 1023;
    float hs = h0[idx];
#pragma unroll
    for (int s = 0; s < NSEG; s++) {
        int k = ((b * NSEG + s) << 10) + j;
        g_segS[k] = hs;
        hs = fmaf(g_segP[k], hs, g_segH[k]);
    }
    if (hlast) hlast[idx] = hs;
}

// ---------------------------------------------------------------------------
__global__ void scan_pass3() {
    int idx = blockIdx.x * blockDim.x + threadIdx.x;   // 0..65535
    int j = idx & 1023;
    int s = (idx >> 10) & (NSEG - 1);
    int b = idx >> (10 + 4);
    float hs = g_segS[idx];
    size_t base = (((size_t)b * T_LEN + (size_t)s * SEGLEN) << 10) + j;
    const float* ap = g_a + base;
    float* hp = g_h + base;
    float P = 1.0f;
#pragma unroll 4
    for (int t = 0; t < SEGLEN; t++) {
        size_t off = (size_t)t << 10;
        P *= ap[off];
        float h = fmaf(P, hs, hp[off]);
        hp[off] = __uint_as_float(f2tf32(h));
    }
}

// ---------------------------------------------------------------------------
extern "C" void kernel_launch(void* const* d_in, const int* in_sizes, int n_in,
                              void* d_out, int out_size) {
    const float* x       = (const float*)d_in[0];
    const float* h_prev  = (const float*)d_in[1];
    const float* gate_w  = (const float*)d_in[2];
    const float* gate_b  = (const float*)d_in[3];
    const float* value_w = (const float*)d_in[4];
    const float* out_w   = (const float*)d_in[5];
    float* out = (float*)d_out;

    float *p_gates, *p_v, *p_h, *p_xc, *p_gwc, *p_vwc, *p_owc;
    cudaGetSymbolAddress((void**)&p_gates, g_gates);
    cudaGetSymbolAddress((void**)&p_v, g_v);
    cudaGetSymbolAddress((void**)&p_h, g_h);
    cudaGetSymbolAddress((void**)&p_xc, g_xc);
    cudaGetSymbolAddress((void**)&p_gwc, g_gwc);
    cudaGetSymbolAddress((void**)&p_vwc, g_vwc);
    cudaGetSymbolAddress((void**)&p_owc, g_owc);

    static bool attr_done = false;
    if (!attr_done) {
        cudaFuncSetAttribute(gemm_tf32_mma,
                             cudaFuncAttributeMaxDynamicSharedMemorySize,
                             NSTAGE * STG_FLTS * 2 * 4);
        attr_done = true;
    }
    const size_t SMEM = NSTAGE * STG_FLTS * 2 * 4;   // 81920

    // tf32 pre-rounding
    {
        int n4;
        n4 = (M_TOT * D_MODEL) / 4;
        convert_tf32<<<(n4 + 255) / 256, 256>>>(x, p_xc, n4);
        n4 = (NGATES * D_MODEL) / 4;
        convert_tf32<<<(n4 + 255) / 256, 256>>>(gate_w, p_gwc, n4);
        n4 = (HS * D_MODEL) / 4;
        convert_tf32<<<(n4 + 255) / 256, 256>>>(value_w, p_vwc, n4);
        n4 = (D_MODEL * HS) / 4;
        convert_tf32<<<(n4 + 255) / 256, 256>>>(out_w, p_owc, n4);
    }
    // Fused GEMM1: [gates | V] = x @ [gate_w | value_w]^T
    {
        dim3 grid(NGATES / 128 + HS / 128, M_TOT / 128);   // 24 x 128
        gemm_tf32_mma<<<grid, 128, SMEM>>>(p_xc, p_gwc, p_vwc, p_gates, p_v,
                                           NGATES / 128, NGATES, HS, D_MODEL);
    }
    // Segmented scan (sigmoid fused into pass 1)
    {
        float* hlast = nullptr;
        if ((size_t)out_size >= (size_t)M_TOT * D_MODEL + BATCH * HS)
            hlast = out + (size_t)M_TOT * D_MODEL;
        scan_pass1<<<(BATCH * NSEG * HS) / 256, 256>>>(gate_b);
        scan_pass2<<<(BATCH * HS) / 256, 256>>>(h_prev, hlast);
        scan_pass3<<<(BATCH * NSEG * HS) / 256, 256>>>();
    }
    // GEMM2: y = h @ out_w^T
    {
        dim3 grid(D_MODEL / 128, M_TOT / 128);
        gemm_tf32_mma<<<grid, 128, SMEM>>>(p_h, p_owc, p_owc, out, out,
                                           D_MODEL / 128, D_MODEL, D_MODEL, D_MODEL);
    }
}

// round 7
// speedup vs baseline: 7.0798x; 1.6560x over previous
#include <cuda_runtime.h>
#include <cuda_fp16.h>
#include <cstdint>

// Problem constants (GLALayer: B=4, T=4096, D_MODEL=1024, H=16, S=64)
#define D_MODEL 1024
#define T_LEN   4096
#define BATCH   4
#define M_TOT   (BATCH * T_LEN)   // 16384
#define HS      1024
#define NGATES  2048

#define NSEG    16
#define SEGLEN  (T_LEN / NSEG)    // 256

// Scratch (device globals)
__device__ __half g_gates[(size_t)M_TOT * NGATES];  // fp16 gate pre-activations
__device__ __half g_v[(size_t)M_TOT * HS];          // fp16 V
__device__ float  g_a[(size_t)M_TOT * HS];          // fp32 forget gates
__device__ float  g_h32[(size_t)M_TOT * HS];        // fp32 local h (pass1)
__device__ __half g_hh[(size_t)M_TOT * HS];         // fp16 final h (GEMM2 input)
__device__ __half g_xh[(size_t)M_TOT * D_MODEL];    // fp16 x
__device__ __half g_gwh[(size_t)NGATES * D_MODEL];
__device__ __half g_vwh[(size_t)HS * D_MODEL];
__device__ __half g_owh[(size_t)D_MODEL * HS];
__device__ float g_segP[BATCH * NSEG * HS];
__device__ float g_segH[BATCH * NSEG * HS];
__device__ float g_segS[BATCH * NSEG * HS];

// ---------------------------------------------------------------------------
__device__ __forceinline__ uint32_t smem_u32(const void* p) {
    uint32_t a;
    asm("{ .reg .u64 t; cvta.to.shared.u64 t, %1; cvt.u32.u64 %0, t; }"
        : "=r"(a) : "l"(p));
    return a;
}

__device__ __forceinline__ void cpasync16(uint32_t dst, const void* src) {
    asm volatile("cp.async.cg.shared.global [%0], [%1], 16;" :: "r"(dst), "l"(src));
}
#define CP_COMMIT()  asm volatile("cp.async.commit_group;" ::: "memory")
#define CP_WAIT(n)   asm volatile("cp.async.wait_group %0;" :: "n"(n) : "memory")

// byte-offset swizzle within an 8 KB stage (rows of 64 B)
__device__ __forceinline__ uint32_t sw64(uint32_t o) {
    return o ^ ((o >> 3) & 0x70);
}

__device__ __forceinline__ void mma_f16(float* c, const uint32_t* a, const uint32_t* b) {
    asm volatile(
        "mma.sync.aligned.m16n8k16.row.col.f32.f16.f16.f32 "
        "{%0,%1,%2,%3}, {%4,%5,%6,%7}, {%8,%9}, {%0,%1,%2,%3};"
        : "+f"(c[0]), "+f"(c[1]), "+f"(c[2]), "+f"(c[3])
        : "r"(a[0]), "r"(a[1]), "r"(a[2]), "r"(a[3]),
          "r"(b[0]), "r"(b[1]));
}

// ---------------------------------------------------------------------------
// TN GEMM fp16 mma.sync, fused dual-output: N-tiles [0,nsplit) -> B1/C1,
// rest -> B2/C2. CTA 128x128, 128 thr, warp tile 64x64. 4-stage cp.async,
// 32-half K stage (64 B/row). K mult of 64. Output f32 or f16 (template).
// ---------------------------------------------------------------------------
#define KTH       32                 // halfs per stage
#define STG_BYTES (128 * 64)         // 8192 per operand stage
#define NSTAGE    4
// dyn smem: NSTAGE * STG_BYTES * 2 = 65536 B

template<bool HALF_OUT>
__global__ void __launch_bounds__(128, 2)
gemm_f16_mma(const __half* __restrict__ A,
             const __half* __restrict__ B1, const __half* __restrict__ B2,
             void* __restrict__ C1, void* __restrict__ C2,
             int nsplit, int N1, int N2, int K) {
    extern __shared__ char smem[];
    const uint32_t sA_u = smem_u32(smem);
    const uint32_t sB_u = sA_u + NSTAGE * STG_BYTES;

    const int tid = threadIdx.x;
    const int lane = tid & 31;
    const int wid = tid >> 5;
    const int wm = (wid >> 1) * 64;
    const int wn = (wid & 1) * 64;
    const int g = lane >> 2;
    const int tg = lane & 3;

    const int bx = blockIdx.x, by = blockIdx.y;

    const __half* Bb;
    void* Cout;
    int Nout, colbase;
    if (bx < nsplit) {
        Bb = B1 + (size_t)bx * 128 * K;
        Cout = C1; Nout = N1; colbase = bx * 128;
    } else {
        Bb = B2 + (size_t)(bx - nsplit) * 128 * K;
        Cout = C2; Nout = N2; colbase = (bx - nsplit) * 128;
    }
    const __half* Ab = A + (size_t)by * 128 * K;

    float acc[4][8][4];
#pragma unroll
    for (int mi = 0; mi < 4; mi++)
#pragma unroll
        for (int ni = 0; ni < 8; ni++)
#pragma unroll
            for (int q = 0; q < 4; q++) acc[mi][ni][q] = 0.0f;

    const int NT = K / KTH;

    // stage load: 512 x 16B granules per operand over 128 threads = 4 each
    auto issue_stage = [&](int kt) {
        const int kof = kt * KTH;
        const uint32_t soff = (uint32_t)((kt & (NSTAGE - 1)) * STG_BYTES);
#pragma unroll
        for (int i = 0; i < 4; i++) {
            const int gid = tid + i * 128;      // 0..511
            const int row = gid >> 2;
            const int q = gid & 3;
            const uint32_t d = soff + sw64((uint32_t)(row * 64 + q * 16));
            cpasync16(sA_u + d, Ab + (size_t)row * K + kof + q * 8);
            cpasync16(sB_u + d, Bb + (size_t)row * K + kof + q * 8);
        }
        CP_COMMIT();
    };

    issue_stage(0);
    issue_stage(1);
    issue_stage(2);

    for (int kt = 0; kt < NT; kt++) {
        CP_WAIT(2);
        __syncthreads();

        const uint32_t aoff = sA_u + (uint32_t)((kt & (NSTAGE - 1)) * STG_BYTES);
        const uint32_t boff = sB_u + (uint32_t)((kt & (NSTAGE - 1)) * STG_BYTES);
#pragma unroll
        for (int ks = 0; ks < 2; ks++) {
            const int kb = ks * 32;             // 16 halfs = 32 B
            uint32_t af[4][4], bf[8][2];
#pragma unroll
            for (int mi = 0; mi < 4; mi++) {
                const int r = (wm + mi * 16 + g) * 64;
                const uint32_t o0 = (uint32_t)(r + kb + 4 * tg);
                af[mi][0] = *(const uint32_t*)__cvta_shared_to_generic(aoff + sw64(o0));
                af[mi][1] = *(const uint32_t*)__cvta_shared_to_generic(aoff + sw64(o0 + 512));
                af[mi][2] = *(const uint32_t*)__cvta_shared_to_generic(aoff + sw64(o0 + 16));
                af[mi][3] = *(const uint32_t*)__cvta_shared_to_generic(aoff + sw64(o0 + 528));
            }
#pragma unroll
            for (int ni = 0; ni < 8; ni++) {
                const int r = (wn + ni * 8 + g) * 64;
                const uint32_t o0 = (uint32_t)(r + kb + 4 * tg);
                bf[ni][0] = *(const uint32_t*)__cvta_shared_to_generic(boff + sw64(o0));
                bf[ni][1] = *(const uint32_t*)__cvta_shared_to_generic(boff + sw64(o0 + 16));
            }
#pragma unroll
            for (int mi = 0; mi < 4; mi++)
#pragma unroll
                for (int ni = 0; ni < 8; ni++)
                    mma_f16(acc[mi][ni], af[mi], bf[ni]);
        }
        __syncthreads();
        if (kt + 3 < NT) issue_stage(kt + 3);
    }

    // Epilogue
#pragma unroll
    for (int mi = 0; mi < 4; mi++) {
        const int row0 = by * 128 + wm + mi * 16 + g;
#pragma unroll
        for (int ni = 0; ni < 8; ni++) {
            const int col = colbase + wn + ni * 8 + 2 * tg;
            if (HALF_OUT) {
                __half* Ch = (__half*)Cout;
                *(__half2*)(Ch + (size_t)row0 * Nout + col) =
                    __floats2half2_rn(acc[mi][ni][0], acc[mi][ni][1]);
                *(__half2*)(Ch + (size_t)(row0 + 8) * Nout + col) =
                    __floats2half2_rn(acc[mi][ni][2], acc[mi][ni][3]);
            } else {
                float* Cf = (float*)Cout;
                *(float2*)(Cf + (size_t)row0 * Nout + col) =
                    make_float2(acc[mi][ni][0], acc[mi][ni][1]);
                *(float2*)(Cf + (size_t)(row0 + 8) * Nout + col) =
                    make_float2(acc[mi][ni][2], acc[mi][ni][3]);
            }
        }
    }
}

// ---------------------------------------------------------------------------
__global__ void convert_f16(const float* __restrict__ src,
                            __half* __restrict__ dst, int n2) {
    int i = blockIdx.x * blockDim.x + threadIdx.x;
    if (i >= n2) return;
    float2 v = ((const float2*)src)[i];
    ((__half2*)dst)[i] = __floats2half2_rn(v.x, v.y);
}

// ---------------------------------------------------------------------------
// Segmented scan pass 1 (fused sigmoid): reads fp16 gates + V.
// ---------------------------------------------------------------------------
__global__ void scan_pass1(const float* __restrict__ gate_b) {
    int idx = blockIdx.x * blockDim.x + threadIdx.x;   // 0..65535
    int j = idx & 1023;
    int s = (idx >> 10) & (NSEG - 1);
    int b = idx >> (10 + 4);
    size_t row0 = (size_t)b * T_LEN + (size_t)s * SEGLEN;
    const __half* gp = g_gates + row0 * NGATES + j;
    const __half* vp = g_v + (row0 << 10) + j;
    float* ap_o = g_a + (row0 << 10) + j;
    float* hp = g_h32 + (row0 << 10) + j;
    const float bfg = gate_b[j];
    const float big = gate_b[HS + j];
    float h = 0.0f, P = 1.0f;
#pragma unroll 4
    for (int t = 0; t < SEGLEN; t++) {
        float gf = __half2float(gp[(size_t)t * NGATES]) + bfg;
        float gi = __half2float(gp[(size_t)t * NGATES + HS]) + big;
        float a = 1.0f / (1.0f + __expf(-gf));
        float bg = 1.0f / (1.0f + __expf(-gi));
        float bv = bg * __half2float(vp[(size_t)t << 10]);
        h = fmaf(a, h, bv);
        P *= a;
        ap_o[(size_t)t << 10] = a;
        hp[(size_t)t << 10] = h;
    }
    g_segP[idx] = P;
    g_segH[idx] = h;
}

// ---------------------------------------------------------------------------
__global__ void scan_pass2(const float* __restrict__ h0,
                           float* __restrict__ hlast) {
    int idx = blockIdx.x * blockDim.x + threadIdx.x;   // 0..4095
    int b = idx >> 10;
    int j = idx & 1023;
    float hs = h0[idx];
#pragma unroll
    for (int s = 0; s < NSEG; s++) {
        int k = ((b * NSEG + s) << 10) + j;
        g_segS[k] = hs;
        hs = fmaf(g_segP[k], hs, g_segH[k]);
    }
    if (hlast) hlast[idx] = hs;
}

// ---------------------------------------------------------------------------
// Pass 3: h_t = local_t + (prod a) * h_segstart -> fp16 for GEMM2.
// ---------------------------------------------------------------------------
__global__ void scan_pass3() {
    int idx = blockIdx.x * blockDim.x + threadIdx.x;   // 0..65535
    int j = idx & 1023;
    int s = (idx >> 10) & (NSEG - 1);
    int b = idx >> (10 + 4);
    float hs = g_segS[idx];
    size_t base = (((size_t)b * T_LEN + (size_t)s * SEGLEN) << 10) + j;
    const float* ap = g_a + base;
    const float* hp = g_h32 + base;
    __half* ho = g_hh + base;
    float P = 1.0f;
#pragma unroll 4
    for (int t = 0; t < SEGLEN; t++) {
        size_t off = (size_t)t << 10;
        P *= ap[off];
        ho[off] = __float2half_rn(fmaf(P, hs, hp[off]));
    }
}

// ---------------------------------------------------------------------------
extern "C" void kernel_launch(void* const* d_in, const int* in_sizes, int n_in,
                              void* d_out, int out_size) {
    const float* x       = (const float*)d_in[0];
    const float* h_prev  = (const float*)d_in[1];
    const float* gate_w  = (const float*)d_in[2];
    const float* gate_b  = (const float*)d_in[3];
    const float* value_w = (const float*)d_in[4];
    const float* out_w   = (const float*)d_in[5];
    float* out = (float*)d_out;

    __half *p_gates, *p_v, *p_hh, *p_xh, *p_gwh, *p_vwh, *p_owh;
    cudaGetSymbolAddress((void**)&p_gates, g_gates);
    cudaGetSymbolAddress((void**)&p_v, g_v);
    cudaGetSymbolAddress((void**)&p_hh, g_hh);
    cudaGetSymbolAddress((void**)&p_xh, g_xh);
    cudaGetSymbolAddress((void**)&p_gwh, g_gwh);
    cudaGetSymbolAddress((void**)&p_vwh, g_vwh);
    cudaGetSymbolAddress((void**)&p_owh, g_owh);

    static bool attr_done = false;
    if (!attr_done) {
        cudaFuncSetAttribute(gemm_f16_mma<true>,
                             cudaFuncAttributeMaxDynamicSharedMemorySize,
                             NSTAGE * STG_BYTES * 2);
        cudaFuncSetAttribute(gemm_f16_mma<false>,
                             cudaFuncAttributeMaxDynamicSharedMemorySize,
                             NSTAGE * STG_BYTES * 2);
        attr_done = true;
    }
    const size_t SMEM = NSTAGE * STG_BYTES * 2;   // 65536

    // fp16 conversions
    {
        int n2;
        n2 = (M_TOT * D_MODEL) / 2;
        convert_f16<<<(n2 + 255) / 256, 256>>>(x, p_xh, n2);
        n2 = (NGATES * D_MODEL) / 2;
        convert_f16<<<(n2 + 255) / 256, 256>>>(gate_w, p_gwh, n2);
        n2 = (HS * D_MODEL) / 2;
        convert_f16<<<(n2 + 255) / 256, 256>>>(value_w, p_vwh, n2);
        n2 = (D_MODEL * HS) / 2;
        convert_f16<<<(n2 + 255) / 256, 256>>>(out_w, p_owh, n2);
    }
    // Fused GEMM1: [gates | V] = x @ [gate_w | value_w]^T  (fp16 outputs)
    {
        dim3 grid(NGATES / 128 + HS / 128, M_TOT / 128);   // 24 x 128
        gemm_f16_mma<true><<<grid, 128, SMEM>>>(p_xh, p_gwh, p_vwh,
                                                p_gates, p_v,
                                                NGATES / 128, NGATES, HS, D_MODEL);
    }
    // Segmented scan
    {
        float* hlast = nullptr;
        if ((size_t)out_size >= (size_t)M_TOT * D_MODEL + BATCH * HS)
            hlast = out + (size_t)M_TOT * D_MODEL;
        scan_pass1<<<(BATCH * NSEG * HS) / 256, 256>>>(gate_b);
        scan_pass2<<<(BATCH * HS) / 256, 256>>>(h_prev, hlast);
        scan_pass3<<<(BATCH * NSEG * HS) / 256, 256>>>();
    }
    // GEMM2: y = h @ out_w^T  (fp32 output)
    {
        dim3 grid(D_MODEL / 128, M_TOT / 128);
        gemm_f16_mma<false><<<grid, 128, SMEM>>>(p_hh, p_owh, p_owh, out, out,
                                                 D_MODEL / 128, D_MODEL, D_MODEL, D_MODEL);
    }
}